// round 17
// baseline (speedup 1.0000x reference)
#include <cuda_runtime.h>
#include <cstdint>

// Bit-exact XLA:CPU(Eigen) emulation of encoder + VQ; fast fp32 decoder.
// FFMA2 (fma.rn.f32x2) per-lane identical rounding to scalar FFMA; all
// reference-matching chains keep exact bits. This round: FMA-bound tiles
// (4pix x 8oc), conflict-free LDS.128 operand feeds, 4-ic staging in decoder.

#define NB    8
#define CH    256
#define NPIX  (NB * 64 * 64)

typedef unsigned long long u64;

__device__ float g_h  [NB * 128 * 128 * CH];  // NHWC h
__device__ float g_ze [NPIX * CH];            // flat z_e rows
__device__ float g_d  [NB * CH * 128 * 128];  // decoder intermediate
__device__ float g_wt [4096 * 256];           // e2 w: [k=(kh*4+kw)*256+ic][oc]
__device__ float g_cn [1024];
__device__ float g_nf [NPIX];
__device__ u64   g_key[NPIX];

// ---- f32x2 helpers (per-lane rn, bit-identical to scalar) ------------------
__device__ __forceinline__ u64 pk2(float lo, float hi) {
    u64 r; asm("mov.b64 %0, {%1, %2};" : "=l"(r) : "f"(lo), "f"(hi)); return r;
}
__device__ __forceinline__ float2 upk2(u64 v) {
    float2 r; asm("mov.b64 {%0, %1}, %2;" : "=f"(r.x), "=f"(r.y) : "l"(v)); return r;
}
__device__ __forceinline__ u64 ffma2(u64 a, u64 b, u64 c) {
    u64 d; asm("fma.rn.f32x2 %0, %1, %2, %3;" : "=l"(d) : "l"(a), "l"(b), "l"(c)); return d;
}
__device__ __forceinline__ u64 fadd2(u64 a, u64 b) {
    u64 d; asm("add.rn.f32x2 %0, %1, %2;" : "=l"(d) : "l"(a), "l"(b)); return d;
}

__global__ void k_init(int base) {
    g_key[base + blockIdx.x * 256 + threadIdx.x] = ~0ULL;
}

__global__ void k_w2t(const float* __restrict__ w2) {
    int gid = blockIdx.x * 256 + threadIdx.x;     // 1,048,576
    int oc = gid & 255, k = gid >> 8;
    int ic = k & 255, kwh = k >> 8;
    g_wt[gid] = w2[(oc * 256 + ic) * 16 + kwh];
}

// cn: strict scalar sequential (reference-matching; PASSED)
__global__ void k_cn(const float* __restrict__ cb) {
    int code = blockIdx.x * 32 + threadIdx.x;
    float s = 0.f;
#pragma unroll 8
    for (int c = 0; c < CH; c++) {
        float v = __ldg(cb + code * CH + c);
        s = __fadd_rn(s, __fmul_rn(v, v));
    }
    g_cn[code] = s;
}

// ---- e1: exact chain over (kh,kw); NHWC stores -----------------------------
__global__ __launch_bounds__(256) void k_conv1x(const float* __restrict__ x,
                                                const float* __restrict__ w1,
                                                const float* __restrict__ b1) {
    __shared__ float sx[4][258];
    const int oh = blockIdx.x, b = blockIdx.y, tx = threadIdx.x;
#pragma unroll
    for (int r = 0; r < 4; r++) {
        int ih = 2 * oh - 1 + r;
        for (int c = tx; c < 258; c += 256) {
            int iw = c - 1;
            sx[r][c] = (unsigned(ih) < 256u && unsigned(iw) < 256u)
                           ? x[b * 65536 + ih * 256 + iw] : 0.f;
        }
    }
    __syncthreads();
    const int oc = tx;
    float wreg[16];
#pragma unroll
    for (int t = 0; t < 16; t++) wreg[t] = __ldg(w1 + oc * 16 + t);
    const float bv = __ldg(b1 + oc);
    float* hrow = g_h + (long)((b * 128 + oh) * 128) * 256 + oc;
    for (int ow = 0; ow < 128; ow++) {
        float acc = 0.f;
#pragma unroll
        for (int t = 0; t < 16; t++)
            acc = __fmaf_rn(sx[t >> 2][2 * ow + (t & 3)], wreg[t], acc);
        hrow[(long)ow * 256] = fmaxf(__fadd_rn(acc, bv), 0.f);
    }
}

// ---- e2: exact chains, 4 pix x 8 oc per thread, FMA-bound ------------------
// Block = 64 pix x 128 oc at (b,oh). Thread oc set: {4j..4j+3, 64+4j..64+4j+3}
// packed as 4 f32x2 pairs. k ascending (kh,kw,icb,ic); fold every 256 (kh,kw).
__global__ __launch_bounds__(256) void k_conv2x(const float* __restrict__ b2) {
    __shared__ __align__(16) float a_s[32][68];    // [ic][pix] (transposed)
    __shared__ __align__(16) float w_s[32][132];   // [ic][oc]  row 528B
    const int ocb = blockIdx.x, oh = blockIdx.y, b = blockIdx.z;
    const int tx = threadIdx.x, i = tx >> 4, j = tx & 15;
    u64 accR[16] = {}, accP[16] = {};              // [p*4 + h]

    for (int kh = 0; kh < 4; kh++) {
        const int ih = 2 * oh - 1 + kh;
        const bool okh = (unsigned(ih) < 128u);
        const long hbase = (long)((b * 128 + ih) * 128) * 256;
        for (int kw = 0; kw < 4; kw++) {
            for (int icb = 0; icb < 8; icb++) {
                __syncthreads();
#pragma unroll
                for (int s = 0; s < 2; s++) {              // a: 64pix x 32ic
                    int t2 = tx + s * 256;                 // 0..511
                    int pix = t2 >> 3, q = t2 & 7;
                    int iw = 2 * pix + kw - 1;
                    float4 v = make_float4(0.f, 0.f, 0.f, 0.f);
                    if (okh && unsigned(iw) < 128u)
                        v = *(const float4*)&g_h[hbase + (long)iw * 256 + icb * 32 + q * 4];
                    a_s[q * 4 + 0][pix] = v.x; a_s[q * 4 + 1][pix] = v.y;
                    a_s[q * 4 + 2][pix] = v.z; a_s[q * 4 + 3][pix] = v.w;
                }
#pragma unroll
                for (int s = 0; s < 4; s++) {              // w: 32ic x 128oc
                    int t2 = tx + s * 256;                 // 0..1023
                    int ic = t2 >> 5, q = t2 & 31;
                    *(float4*)&w_s[ic][q * 4] = *(const float4*)
                        &g_wt[(long)((kh * 4 + kw) * 256 + icb * 32 + ic) * 256 + ocb * 128 + q * 4];
                }
                __syncthreads();
#pragma unroll 4
                for (int ic = 0; ic < 32; ic++) {
                    ulonglong2 wA = *(const ulonglong2*)&w_s[ic][j * 4];
                    ulonglong2 wB = *(const ulonglong2*)&w_s[ic][64 + j * 4];
                    float4 a4 = *(const float4*)&a_s[ic][i * 4];
                    float av[4] = {a4.x, a4.y, a4.z, a4.w};
#pragma unroll
                    for (int p = 0; p < 4; p++) {
                        u64 aa = pk2(av[p], av[p]);
                        accP[p * 4 + 0] = ffma2(aa, wA.x, accP[p * 4 + 0]);
                        accP[p * 4 + 1] = ffma2(aa, wA.y, accP[p * 4 + 1]);
                        accP[p * 4 + 2] = ffma2(aa, wB.x, accP[p * 4 + 2]);
                        accP[p * 4 + 3] = ffma2(aa, wB.y, accP[p * 4 + 3]);
                    }
                }
            }
#pragma unroll
            for (int t = 0; t < 16; t++) {         // panel fold (k % 256 == 0)
                accR[t] = fadd2(accR[t], accP[t]);
                accP[t] = 0ULL;
            }
        }
    }
#pragma unroll
    for (int p = 0; p < 4; p++) {
        int pix = ((b * 64 + oh) * 64) + i * 4 + p;
#pragma unroll
        for (int h = 0; h < 4; h++) {
            int oc = ocb * 128 + (h >> 1) * 64 + j * 4 + (h & 1) * 2;
            float2 r = upk2(accR[p * 4 + h]);
            float b0 = __ldg(b2 + oc), b1 = __ldg(b2 + oc + 1);
            g_ze[(long)pix * 256 + oc]     = fmaxf(__fadd_rn(r.x, b0), 0.f);
            g_ze[(long)pix * 256 + oc + 1] = fmaxf(__fadd_rn(r.y, b1), 0.f);
        }
    }
}

// ---- ff: 4-lane vector + ordered horizontal (reference-matching) -----------
__global__ void k_ff() {
    int pix = blockIdx.x * 256 + threadIdx.x;
    const float* f = g_ze + (long)pix * 256;
    float v[4] = {};
#pragma unroll 8
    for (int i = 0; i < 64; i++) {
#pragma unroll
        for (int l = 0; l < 4; l++) {
            float x = __ldg(f + 4 * i + l);
            v[l] = __fadd_rn(v[l], __fmul_rn(x, x));
        }
    }
    g_nf[pix] = __fadd_rn(__fadd_rn(__fadd_rn(v[0], v[1]), v[2]), v[3]);
}

__device__ __forceinline__ unsigned fkey(float f) {
    unsigned u = __float_as_uint(f);
    return (u & 0x80000000u) ? ~u : (u | 0x80000000u);
}

// ---- fused dot GEMM + bit-exact dist + argmin ------------------------------
// 64 pix x 128 codes per block; thread = 4 pix x 8 codes (split {4j,64+4j}).
// K=256 single ascending FMA chain per output (f32x2 pairs).
__global__ __launch_bounds__(256) void k_dotvq(const float* __restrict__ cb) {
    __shared__ __align__(16) float As[16][68];     // [k][pix]
    __shared__ __align__(16) float Bs[16][132];    // [k][code]
    __shared__ float cs[128];
    const int n0 = blockIdx.x * 128, py = blockIdx.y;
    const int tx = threadIdx.x, i = tx >> 4, j = tx & 15;
    const float* fl = g_ze + (long)py * 64 * 256;

    if (tx < 128) cs[tx] = __ldg(g_cn + n0 + tx);

    u64 acc[16] = {};                              // [p*4 + h]
    for (int kc = 0; kc < 256; kc += 16) {
        __syncthreads();
        {                                          // As: 16k x 64pix
            int pix = tx & 63, kq = tx >> 6;
            float4 v = *(const float4*)&fl[(long)pix * 256 + kc + kq * 4];
            As[kq * 4 + 0][pix] = v.x; As[kq * 4 + 1][pix] = v.y;
            As[kq * 4 + 2][pix] = v.z; As[kq * 4 + 3][pix] = v.w;
        }
#pragma unroll
        for (int s = 0; s < 2; s++) {              // Bs: 16k x 128code
            int t2 = tx + s * 256;                 // 0..511
            int n = t2 & 127, kq = t2 >> 7;
            float4 v = *(const float4*)&cb[(long)(n0 + n) * 256 + kc + kq * 4];
            Bs[kq * 4 + 0][n] = v.x; Bs[kq * 4 + 1][n] = v.y;
            Bs[kq * 4 + 2][n] = v.z; Bs[kq * 4 + 3][n] = v.w;
        }
        __syncthreads();
#pragma unroll
        for (int k = 0; k < 16; k++) {
            ulonglong2 cA = *(const ulonglong2*)&Bs[k][j * 4];
            ulonglong2 cB = *(const ulonglong2*)&Bs[k][64 + j * 4];
            float4 a4 = *(const float4*)&As[k][i * 4];
            float av[4] = {a4.x, a4.y, a4.z, a4.w};
#pragma unroll
            for (int p = 0; p < 4; p++) {
                u64 aa = pk2(av[p], av[p]);
                acc[p * 4 + 0] = ffma2(aa, cA.x, acc[p * 4 + 0]);
                acc[p * 4 + 1] = ffma2(aa, cA.y, acc[p * 4 + 1]);
                acc[p * 4 + 2] = ffma2(aa, cB.x, acc[p * 4 + 2]);
                acc[p * 4 + 3] = ffma2(aa, cB.y, acc[p * 4 + 3]);
            }
        }
    }

#pragma unroll
    for (int p = 0; p < 4; p++) {
        int pix = py * 64 + i * 4 + p;
        float ff = __ldg(g_nf + pix);
        u64 best = ~0ULL;
#pragma unroll
        for (int h = 0; h < 4; h++) {
            float2 dpair = upk2(acc[p * 4 + h]);
            float dots[2] = {dpair.x, dpair.y};
            int cbase = (h >> 1) * 64 + j * 4 + (h & 1) * 2;
#pragma unroll
            for (int q = 0; q < 2; q++) {
                int code = n0 + cbase + q;
                float t = __fadd_rn(ff, -__fmul_rn(2.f, dots[q]));
                float d = __fadd_rn(t, cs[cbase + q]);
                u64 key = ((u64)fkey(d) << 32) | (unsigned)code;
                if (key < best) best = key;
            }
        }
#pragma unroll
        for (int m = 8; m >= 1; m >>= 1) {
            u64 o = __shfl_xor_sync(0xffffffffu, best, m);
            if (o < best) best = o;
        }
        if (j == 0) atomicMin(&g_key[pix], best);
    }
}

// ---- z_q gather: planar NCHW into d_out ------------------------------------
__global__ void k_gather(const float* __restrict__ cb, float* __restrict__ zq) {
    int gid = blockIdx.x * 256 + threadIdx.x;     // 8,388,608
    int w = gid & 63, hh = (gid >> 6) & 63, c = (gid >> 12) & 255, b = gid >> 20;
    int pix = (b << 12) | (hh << 6) | w;
    int code = (int)(g_key[pix] & 0xffffffffu);
    zq[gid] = cb[code * CH + c];
}

// ---- d1: ConvT subpixel, 4-ic staging, LDS.128 feeds -----------------------
__global__ __launch_bounds__(256) void k_dconv1(const float* __restrict__ zq,
                                                const float* __restrict__ w,
                                                const float* __restrict__ bias) {
    __shared__ __align__(16) float patch4[4][2][68];
    __shared__ __align__(16) float wst4[4][16][64];   // [icq][tap][oc]
    const int oc0 = blockIdx.x * 64, oh = blockIdx.y, b = blockIdx.z;
    const int a = (oh + 1) & 1;
    const int ih1 = (oh + 1 - a) >> 1;
    const int tx = threadIdx.x, i = tx >> 4, j = tx & 15;
    u64 acc[8][2] = {};                               // [pix][oc-pair]

    for (int icg = 0; icg < 64; icg++) {
        const int ic0 = icg * 4;
        __syncthreads();
        for (int t = tx; t < 528; t += 256) {
            int icq = t / 132, rem = t - icq * 132;
            int r = rem / 66, c = rem - r * 66;
            int ih = ih1 - 1 + r, iw = c - 1;
            patch4[icq][r][c] = (unsigned(ih) < 64u && unsigned(iw) < 64u)
                ? zq[((b * CH + ic0 + icq) * 64 + ih) * 64 + iw] : 0.f;
        }
#pragma unroll
        for (int s = 0; s < 4; s++) {
            int t2 = tx + s * 256;                    // 0..1023
            int icq = t2 >> 8, ocl = t2 & 63, kk = ((t2 >> 6) & 3) * 4;
            float4 v = *(const float4*)&w[(((ic0 + icq) * CH + oc0 + ocl) << 4) + kk];
            wst4[icq][kk + 0][ocl] = v.x; wst4[icq][kk + 1][ocl] = v.y;
            wst4[icq][kk + 2][ocl] = v.z; wst4[icq][kk + 3][ocl] = v.w;
        }
        __syncthreads();
#pragma unroll
        for (int icq = 0; icq < 4; icq++) {
            float4 A0 = *(const float4*)&patch4[icq][0][4 * i];
            float2 B0 = *(const float2*)&patch4[icq][0][4 * i + 4];
            float4 A1 = *(const float4*)&patch4[icq][1][4 * i];
            float2 B1 = *(const float2*)&patch4[icq][1][4 * i + 4];
            float r0[6] = {A0.x, A0.y, A0.z, A0.w, B0.x, B0.y};
            float r1[6] = {A1.x, A1.y, A1.z, A1.w, B1.x, B1.y};
            ulonglong2 wA[4], wB[4];
#pragma unroll
            for (int kw = 0; kw < 4; kw++) {
                wA[kw] = *(const ulonglong2*)&wst4[icq][a * 4 + kw][j * 4];
                wB[kw] = *(const ulonglong2*)&wst4[icq][(a + 2) * 4 + kw][j * 4];
            }
#pragma unroll
            for (int pp = 0; pp < 8; pp++) {
                int lo = (pp + 1) >> 1, hi = lo + 1;
                int kwa = (pp & 1) ? 0 : 1, kwb = kwa + 2;
                u64 vh1 = pk2(r1[hi], r1[hi]), vl1 = pk2(r1[lo], r1[lo]);
                u64 vh0 = pk2(r0[hi], r0[hi]), vl0 = pk2(r0[lo], r0[lo]);
                {
                    u64 s = acc[pp][0];
                    s = ffma2(vh1, wA[kwa].x, s);
                    s = ffma2(vl1, wA[kwb].x, s);
                    s = ffma2(vh0, wB[kwa].x, s);
                    s = ffma2(vl0, wB[kwb].x, s);
                    acc[pp][0] = s;
                }
                {
                    u64 s = acc[pp][1];
                    s = ffma2(vh1, wA[kwa].y, s);
                    s = ffma2(vl1, wA[kwb].y, s);
                    s = ffma2(vh0, wB[kwa].y, s);
                    s = ffma2(vl0, wB[kwb].y, s);
                    acc[pp][1] = s;
                }
            }
        }
    }
#pragma unroll
    for (int h = 0; h < 2; h++) {
#pragma unroll
        for (int q = 0; q < 2; q++) {
            int oc = oc0 + j * 4 + 2 * h + q;
            float bv = __ldg(bias + oc);
#pragma unroll
            for (int pp = 0; pp < 8; pp++) {
                float2 r = upk2(acc[pp][h]);
                float val = q ? r.y : r.x;
                g_d[((b * CH + oc) * 128 + oh) * 128 + i * 8 + pp] =
                    fmaxf(val + bv, 0.f);
            }
        }
    }
}

// ---- d2: ConvT 256->1, 4-ic staging ----------------------------------------
__global__ void k_dconv2(const float* __restrict__ w,
                         const float* __restrict__ bias,
                         float* __restrict__ out) {
    __shared__ float patch4[4][2][132];
    __shared__ float wsh4[4][2][4];
    const int oh = blockIdx.x, b = blockIdx.y;
    const int a = (oh + 1) & 1;
    const int ih1 = (oh + 1 - a) >> 1;
    const int tx = threadIdx.x;
    const int b0 = 1 - (tx & 1);
    const int col = ((tx + 1 - b0) >> 1) + 1;

    float acc = 0.f;
    for (int icg = 0; icg < 64; icg++) {
        const int ic0 = icg * 4;
        __syncthreads();
        for (int t = tx; t < 1040; t += 256) {
            int icq = t / 260, rem = t - icq * 260;
            int r = rem / 130, c = rem - r * 130;
            int ih = ih1 - 1 + r, iw = c - 1;
            patch4[icq][r][c] = (unsigned(ih) < 128u && unsigned(iw) < 128u)
                ? g_d[((b * CH + ic0 + icq) * 128 + ih) * 128 + iw] : 0.f;
        }
        if (tx < 32) {
            int icq = tx >> 3, r = (tx >> 2) & 1, k = tx & 3;
            wsh4[icq][r][k] = w[(ic0 + icq) * 16 + (a + 2 * r) * 4 + k];
        }
        __syncthreads();
#pragma unroll
        for (int icq = 0; icq < 4; icq++) {
            acc += patch4[icq][1][col]     * wsh4[icq][0][b0]
                 + patch4[icq][1][col - 1] * wsh4[icq][0][b0 + 2]
                 + patch4[icq][0][col]     * wsh4[icq][1][b0]
                 + patch4[icq][0][col - 1] * wsh4[icq][1][b0 + 2];
        }
    }
    out[(b << 16) + oh * 256 + tx] = acc + bias[0];
}

extern "C" void kernel_launch(void* const* d_in, const int* in_sizes, int n_in,
                              void* d_out, int out_size) {
    const float* x   = (const float*)d_in[0];
    const float* e1w = (const float*)d_in[1];
    const float* e1b = (const float*)d_in[2];
    const float* e2w = (const float*)d_in[3];
    const float* e2b = (const float*)d_in[4];
    const float* cb  = (const float*)d_in[5];
    const float* d1w = (const float*)d_in[6];
    const float* d1b = (const float*)d_in[7];
    const float* d2w = (const float*)d_in[8];
    const float* d2b = (const float*)d_in[9];
    float* out = (float*)d_out;
    float* zq  = out + NB * 256 * 256;

    k_init  <<<64, 256>>>(0);
    k_init  <<<64, 256>>>(16384);
    k_cn    <<<32, 32>>>(cb);
    k_w2t   <<<4096, 256>>>(e2w);
    k_conv1x<<<dim3(128, NB), 256>>>(x, e1w, e1b);
    k_conv2x<<<dim3(2, 64, NB), 256>>>(e2b);
    k_ff    <<<128, 256>>>();
    k_dotvq <<<dim3(8, 512), 256>>>(cb);
    k_gather<<<32768, 256>>>(cb, zq);
    k_dconv1<<<dim3(4, 128, NB), 256>>>(zq, d1w, d1b);
    k_dconv2<<<dim3(256, NB), 256>>>(d2w, d2b, out);
}